// round 13
// baseline (speedup 1.0000x reference)
#include <cuda_runtime.h>
#include <cstdint>
#include <math.h>

#define BATCH    4
#define SEQLEN   2048
#define DMODEL   1024
#define DSTATE   64
#define DCONV    4
#define HEADDIM  64
#define DINNER   2048
#define NH       32
#define CONVDIM  2176            // DINNER + 2*DSTATE
#define NPROJ    4256            // 2*DINNER + 2*DSTATE + NH
#define MROWS    (BATCH*SEQLEN)  // 8192

// ---------------- scratch (device globals; no allocation allowed) ----------
__device__ float g_zxbcdt[(size_t)MROWS * NPROJ];   // 139.5 MB
__device__ float g_xbc  [(size_t)MROWS * CONVDIM];  // 71.3 MB
__device__ float g_dt   [(size_t)MROWS * NH];
__device__ float g_y    [(size_t)MROWS * DINNER];   // 67 MB

// ================= tf32 mma.sync helpers (base sm_103 target OK) ===========
__device__ __forceinline__ void split_tf32(float v, float& hi, float& lo) {
    uint32_t h, l;
    asm("cvt.rna.tf32.f32 %0, %1;" : "=r"(h) : "f"(v));
    const float hf = __uint_as_float(h);
    const float lf = v - hf;
    asm("cvt.rna.tf32.f32 %0, %1;" : "=r"(l) : "f"(lf));
    hi = __uint_as_float(h);
    lo = __uint_as_float(l);
}
__device__ __forceinline__ void mma_tf32(float* c, const uint32_t* a, const uint32_t* b) {
    asm volatile(
        "mma.sync.aligned.m16n8k8.row.col.f32.tf32.tf32.f32 "
        "{%0,%1,%2,%3}, {%4,%5,%6,%7}, {%8,%9}, {%0,%1,%2,%3};\n"
        : "+f"(c[0]), "+f"(c[1]), "+f"(c[2]), "+f"(c[3])
        : "r"(a[0]), "r"(a[1]), "r"(a[2]), "r"(a[3]), "r"(b[0]), "r"(b[1]));
}

// ================= 3xTF32 GEMM: C[M,N] = A[M,K] @ B[K,N] ===================
// BM=BN=128, BK=16, 256 threads (8 warps, 4x2 warp grid, 32x64 per warp).
// hi/lo tf32 split done ONCE at staging (stored in smem); inner loop loads
// fragments directly -> no cvt in the hot loop.
// Requires M%128==0, K%16==0, N%4==0. N edge guarded.
#define GBM 128
#define GBN 128
#define GBK 16
#define GPAD 4
#define GSTRIDE (GBK + GPAD)     // 20 floats: conflict-free fragment loads

__global__ __launch_bounds__(256, 1) void gemm_mma_kernel(
    const float* __restrict__ A, const float* __restrict__ B,
    float* __restrict__ C, int M, int N, int K)
{
    __shared__ __align__(16) float AsH[GBM][GSTRIDE];
    __shared__ __align__(16) float AsL[GBM][GSTRIDE];
    __shared__ __align__(16) float BsH[GBN][GSTRIDE];   // [n][k]
    __shared__ __align__(16) float BsL[GBN][GSTRIDE];

    const int tid = threadIdx.x;
    const int wid = tid >> 5;
    const int lane = tid & 31;
    const int lr = lane >> 2;     // 0..7
    const int lc = lane & 3;      // 0..3
    const int wM = (wid & 3) * 32;
    const int wN = (wid >> 2) * 64;
    const int rowBase = blockIdx.x * GBM;
    const int colBase = blockIdx.y * GBN;
    const int KT = K / GBK;

    // global load maps
    const int aRow = tid >> 1;              // 0..127
    const int aK4  = (tid & 1) * 8;         // 0 or 8
    const float* Aptr = A + (size_t)(rowBase + aRow) * K + aK4;
    const int bK  = tid >> 5;               // 0..7 (and +8 on 2nd fetch)
    const int bN4 = (tid & 31) * 4;
    const bool bOk = (colBase + bN4) < N;
    const float* Bptr = B + colBase + bN4;

    float acc[2][8][4];
    #pragma unroll
    for (int mt = 0; mt < 2; mt++)
        #pragma unroll
        for (int nt = 0; nt < 8; nt++)
            #pragma unroll
            for (int q = 0; q < 4; q++) acc[mt][nt][q] = 0.f;

    float4 aR[2], bR[2];
    // prologue: fetch tile 0
    aR[0] = *(const float4*)(Aptr);
    aR[1] = *(const float4*)(Aptr + 4);
    bR[0] = bOk ? *(const float4*)(Bptr + (size_t)bK * N)       : make_float4(0,0,0,0);
    bR[1] = bOk ? *(const float4*)(Bptr + (size_t)(bK + 8) * N) : make_float4(0,0,0,0);

    for (int kt = 0; kt < KT; kt++) {
        __syncthreads();     // previous tile fully consumed
        // split + store staged registers to smem
        {
            float4 h0, l0, h1, l1;
            split_tf32(aR[0].x, h0.x, l0.x); split_tf32(aR[0].y, h0.y, l0.y);
            split_tf32(aR[0].z, h0.z, l0.z); split_tf32(aR[0].w, h0.w, l0.w);
            split_tf32(aR[1].x, h1.x, l1.x); split_tf32(aR[1].y, h1.y, l1.y);
            split_tf32(aR[1].z, h1.z, l1.z); split_tf32(aR[1].w, h1.w, l1.w);
            *(float4*)&AsH[aRow][aK4]     = h0;
            *(float4*)&AsH[aRow][aK4 + 4] = h1;
            *(float4*)&AsL[aRow][aK4]     = l0;
            *(float4*)&AsL[aRow][aK4 + 4] = l1;
            #pragma unroll
            for (int j = 0; j < 4; j++) {
                float bh, bl;
                split_tf32(((const float*)&bR[0])[j], bh, bl);
                BsH[bN4 + j][bK] = bh;  BsL[bN4 + j][bK] = bl;
                split_tf32(((const float*)&bR[1])[j], bh, bl);
                BsH[bN4 + j][bK + 8] = bh;  BsL[bN4 + j][bK + 8] = bl;
            }
        }
        __syncthreads();

        // prefetch next tile into registers (hides L2/DRAM behind mma work)
        if (kt + 1 < KT) {
            const float* ap = Aptr + (kt + 1) * GBK;
            aR[0] = *(const float4*)(ap);
            aR[1] = *(const float4*)(ap + 4);
            const size_t kb = (size_t)(kt + 1) * GBK;
            bR[0] = bOk ? *(const float4*)(Bptr + (kb + bK) * N)     : make_float4(0,0,0,0);
            bR[1] = bOk ? *(const float4*)(Bptr + (kb + bK + 8) * N) : make_float4(0,0,0,0);
        }

        // compute: 2 k-steps of 8, fragments loaded pre-split
        #pragma unroll
        for (int ks = 0; ks < 2; ks++) {
            const int kb = ks * 8;
            uint32_t ahi[2][4], alo[2][4];
            #pragma unroll
            for (int mt = 0; mt < 2; mt++) {
                const int r0 = wM + mt * 16 + lr;
                ahi[mt][0] = __float_as_uint(AsH[r0    ][kb + lc    ]);
                ahi[mt][1] = __float_as_uint(AsH[r0 + 8][kb + lc    ]);
                ahi[mt][2] = __float_as_uint(AsH[r0    ][kb + lc + 4]);
                ahi[mt][3] = __float_as_uint(AsH[r0 + 8][kb + lc + 4]);
                alo[mt][0] = __float_as_uint(AsL[r0    ][kb + lc    ]);
                alo[mt][1] = __float_as_uint(AsL[r0 + 8][kb + lc    ]);
                alo[mt][2] = __float_as_uint(AsL[r0    ][kb + lc + 4]);
                alo[mt][3] = __float_as_uint(AsL[r0 + 8][kb + lc + 4]);
            }
            #pragma unroll
            for (int nt = 0; nt < 8; nt++) {
                const int n0 = wN + nt * 8 + lr;
                uint32_t bhi[2], blo[2];
                bhi[0] = __float_as_uint(BsH[n0][kb + lc    ]);
                bhi[1] = __float_as_uint(BsH[n0][kb + lc + 4]);
                blo[0] = __float_as_uint(BsL[n0][kb + lc    ]);
                blo[1] = __float_as_uint(BsL[n0][kb + lc + 4]);
                #pragma unroll
                for (int mt = 0; mt < 2; mt++) {
                    mma_tf32(acc[mt][nt], ahi[mt], bhi);
                    mma_tf32(acc[mt][nt], ahi[mt], blo);
                    mma_tf32(acc[mt][nt], alo[mt], bhi);
                }
            }
        }
    }

    // epilogue
    #pragma unroll
    for (int mt = 0; mt < 2; mt++) {
        const int r = rowBase + wM + mt * 16 + lr;
        #pragma unroll
        for (int nt = 0; nt < 8; nt++) {
            const int cl = colBase + wN + nt * 8 + 2 * lc;
            if (cl < N) {
                *(float2*)(C + (size_t)r * N + cl) =
                    make_float2(acc[mt][nt][0], acc[mt][nt][1]);
                *(float2*)(C + (size_t)(r + 8) * N + cl) =
                    make_float2(acc[mt][nt][2], acc[mt][nt][3]);
            }
        }
    }
}

// ---------------- causal depthwise conv1d (k=4) + bias + SiLU --------------
__global__ __launch_bounds__(256) void conv_kernel(
    const float* __restrict__ conv_w, const float* __restrict__ conv_b)
{
    const int l = blockIdx.x;
    const int b = blockIdx.y;
    const size_t orow = (size_t)(b * SEQLEN + l);

    for (int c = threadIdx.x; c < CONVDIM; c += 256) {
        float s = conv_b[c];
        #pragma unroll
        for (int k = 0; k < DCONV; k++) {
            const int ls = l - (DCONV - 1) + k;
            if (ls >= 0)
                s = fmaf(g_zxbcdt[((size_t)(b * SEQLEN + ls)) * NPROJ + DINNER + c],
                         conv_w[c * DCONV + k], s);
        }
        const float sil = s / (1.f + __expf(-s));
        g_xbc[orow * CONVDIM + c] = sil;
    }
}

// ---------------- dt = softplus(dt_raw + dt_bias) --------------------------
__global__ __launch_bounds__(256) void dt_kernel(const float* __restrict__ dt_bias)
{
    const int i = blockIdx.x * 256 + threadIdx.x;   // over MROWS*NH
    if (i >= MROWS * NH) return;
    const int h = i & (NH - 1);
    const int row = i >> 5;
    const float v = g_zxbcdt[(size_t)row * NPROJ + (DINNER + CONVDIM) + h] + dt_bias[h];
    g_dt[i] = (v > 20.f) ? v : log1pf(expf(v));
}

// ---------------- sequential selective scan (2-D thread blocking) ----------
// Block = one (b, h). 128 threads: pc = tid>>3 (16 chunks of 4 p-rows),
// nc = tid&7 (8 chunks of 8 states). Each thread owns a 4x8 (p,n) block of
// state in registers -> per-step smem bytes drop ~6.5x vs 1-D layout (L1
// wavefronts = raw bytes on this HW; no broadcast dedup for LDS.128).
// acc reduced over the 8 nc lanes with 3 shfls.
#define SCHUNK 32
__global__ __launch_bounds__(128) void scan_kernel(
    const float* __restrict__ A_log, const float* __restrict__ Dv)
{
    __shared__ float sB[SCHUNK][DSTATE];
    __shared__ float sC[SCHUNK][DSTATE];
    __shared__ float sx[SCHUNK][HEADDIM];
    __shared__ float sdt[SCHUNK];

    const int bh = blockIdx.x;
    const int b = bh >> 5, h = bh & (NH - 1);
    const int tid = threadIdx.x;
    const int nc = tid & 7;          // state chunk: n in [8*nc, 8*nc+8)
    const int pc = tid >> 3;         // p chunk:     p in [4*pc, 4*pc+4)
    const int n0 = nc * 8;
    const int p0 = pc * 4;

    const float Aneg = -__expf(A_log[h]);
    const float Dh   = Dv[h];

    const float* dptr = g_dt + (size_t)b * SEQLEN * NH + h;
    float* ybase = g_y + (size_t)b * SEQLEN * DINNER + h * HEADDIM + p0;

    float hs[4][8];
    #pragma unroll
    for (int p = 0; p < 4; p++)
        #pragma unroll
        for (int j = 0; j < 8; j++) hs[p][j] = 0.f;

    for (int t0 = 0; t0 < SEQLEN; t0 += SCHUNK) {
        __syncthreads();    // previous chunk fully consumed
        // cooperative stage: SCHUNK steps x 64 floats each of B, C, x
        #pragma unroll
        for (int r = 0; r < (SCHUNK * 64 / 128); r++) {
            const int idx = tid + r * 128;
            const int t = idx >> 6, j = idx & 63;
            const size_t rb = (size_t)(b * SEQLEN + t0 + t) * CONVDIM;
            sB[t][j] = g_xbc[rb + DINNER + j];
            sC[t][j] = g_xbc[rb + DINNER + DSTATE + j];
            sx[t][j] = g_xbc[rb + h * HEADDIM + j];
        }
        if (tid < SCHUNK) sdt[tid] = dptr[(size_t)(t0 + tid) * NH];
        __syncthreads();

        #pragma unroll 4
        for (int tt = 0; tt < SCHUNK; tt++) {
            const float dtv = sdt[tt];
            const float dA = __expf(dtv * Aneg);
            const float4 xv = *(const float4*)&sx[tt][p0];
            const float4 b0 = *(const float4*)&sB[tt][n0];
            const float4 b1 = *(const float4*)&sB[tt][n0 + 4];
            const float4 c0 = *(const float4*)&sC[tt][n0];
            const float4 c1 = *(const float4*)&sC[tt][n0 + 4];
            float gb[8];
            gb[0] = dtv * b0.x; gb[1] = dtv * b0.y; gb[2] = dtv * b0.z; gb[3] = dtv * b0.w;
            gb[4] = dtv * b1.x; gb[5] = dtv * b1.y; gb[6] = dtv * b1.z; gb[7] = dtv * b1.w;
            const float cv[8] = {c0.x, c0.y, c0.z, c0.w, c1.x, c1.y, c1.z, c1.w};
            const float xp[4] = {xv.x, xv.y, xv.z, xv.w};
            float acc[4];
            #pragma unroll
            for (int p = 0; p < 4; p++) {
                acc[p] = 0.f;
                #pragma unroll
                for (int j = 0; j < 8; j++) {
                    hs[p][j] = fmaf(hs[p][j], dA, xp[p] * gb[j]);
                    acc[p] = fmaf(hs[p][j], cv[j], acc[p]);
                }
            }
            #pragma unroll
            for (int off = 1; off < 8; off <<= 1) {
                #pragma unroll
                for (int p = 0; p < 4; p++)
                    acc[p] += __shfl_xor_sync(0xffffffffu, acc[p], off);
            }
            if (nc == 0) {
                float4 o;
                o.x = acc[0] + Dh * xp[0];
                o.y = acc[1] + Dh * xp[1];
                o.z = acc[2] + Dh * xp[2];
                o.w = acc[3] + Dh * xp[3];
                *(float4*)(ybase + (size_t)(t0 + tt) * DINNER) = o;
            }
        }
    }
}

// ---------------- y = rmsnorm(y * silu(z)) * norm_w (in place) -------------
__global__ __launch_bounds__(256) void gatenorm_kernel(const float* __restrict__ norm_w)
{
    const int row = blockIdx.x;
    const float* zrow = g_zxbcdt + (size_t)row * NPROJ;   // z = first DINNER cols
    float* yrow = g_y + (size_t)row * DINNER;

    float v[8];
    float ss = 0.f;
    #pragma unroll
    for (int j = 0; j < 8; j++) {
        const int i = threadIdx.x + j * 256;
        const float z = zrow[i];
        const float g = yrow[i] * (z / (1.f + __expf(-z)));
        v[j] = g;
        ss = fmaf(g, g, ss);
    }
    #pragma unroll
    for (int o = 16; o; o >>= 1) ss += __shfl_xor_sync(0xffffffffu, ss, o);

    __shared__ float red[8];
    __shared__ float s_rstd;
    if ((threadIdx.x & 31) == 0) red[threadIdx.x >> 5] = ss;
    __syncthreads();
    if (threadIdx.x == 0) {
        float t = 0.f;
        #pragma unroll
        for (int w = 0; w < 8; w++) t += red[w];
        s_rstd = rsqrtf(t / (float)DINNER + 1e-5f);
    }
    __syncthreads();
    const float rstd = s_rstd;

    #pragma unroll
    for (int j = 0; j < 8; j++) {
        const int i = threadIdx.x + j * 256;
        yrow[i] = v[j] * rstd * norm_w[i];
    }
}

// ---------------- launch ----------------------------------------------------
extern "C" void kernel_launch(void* const* d_in, const int* in_sizes, int n_in,
                              void* d_out, int out_size)
{
    const float* x       = (const float*)d_in[0];
    const float* W_in    = (const float*)d_in[1];
    const float* conv_w  = (const float*)d_in[2];
    const float* conv_b  = (const float*)d_in[3];
    const float* dt_bias = (const float*)d_in[4];
    const float* A_log   = (const float*)d_in[5];
    const float* Dvec    = (const float*)d_in[6];
    const float* norm_w  = (const float*)d_in[7];
    const float* W_out   = (const float*)d_in[8];
    float* out = (float*)d_out;

    void *p_zx, *p_y;
    cudaGetSymbolAddress(&p_zx, g_zxbcdt);
    cudaGetSymbolAddress(&p_y,  g_y);
    float* zx = (float*)p_zx;
    float* y  = (float*)p_y;

    // 1) in-projection: zxbcdt = x @ W_in   [8192,1024]@[1024,4256]
    {
        dim3 grid(MROWS / GBM, (NPROJ + GBN - 1) / GBN);
        gemm_mma_kernel<<<grid, 256>>>(x, W_in, zx, MROWS, NPROJ, DMODEL);
    }
    // 2) conv + SiLU
    conv_kernel<<<dim3(SEQLEN, BATCH), 256>>>(conv_w, conv_b);
    // 3) dt softplus
    dt_kernel<<<(MROWS * NH + 255) / 256, 256>>>(dt_bias);
    // 4) selective scan
    scan_kernel<<<BATCH * NH, 128>>>(A_log, Dvec);
    // 5) gate + rmsnorm (in place on g_y)
    gatenorm_kernel<<<MROWS, 256>>>(norm_w);
    // 6) out-projection: out = y @ W_out   [8192,2048]@[2048,1024]
    {
        dim3 grid(MROWS / GBM, DMODEL / GBN);
        gemm_mma_kernel<<<grid, 256>>>(y, W_out, out, MROWS, DMODEL, DINNER);
    }
}

// round 14
// speedup vs baseline: 1.3419x; 1.3419x over previous
#include <cuda_runtime.h>
#include <cstdint>
#include <math.h>

#define BATCH    4
#define SEQLEN   2048
#define DMODEL   1024
#define DSTATE   64
#define DCONV    4
#define HEADDIM  64
#define DINNER   2048
#define NH       32
#define CONVDIM  2176            // DINNER + 2*DSTATE
#define NPROJ    4256            // 2*DINNER + 2*DSTATE + NH
#define MROWS    (BATCH*SEQLEN)  // 8192

// ---------------- scratch (device globals; no allocation allowed) ----------
__device__ float g_zxbcdt[(size_t)MROWS * NPROJ];   // 139.5 MB
__device__ float g_xbc  [(size_t)MROWS * CONVDIM];  // 71.3 MB
__device__ float g_dt   [(size_t)MROWS * NH];
__device__ float g_y    [(size_t)MROWS * DINNER];   // 67 MB

// ---------------- packed f32x2 helpers (sm_103a FFMA2 path) ----------------
__device__ __forceinline__ unsigned long long pack2(float lo, float hi) {
    unsigned long long r;
    asm("mov.b64 %0, {%1, %2};" : "=l"(r) : "f"(lo), "f"(hi));
    return r;
}
__device__ __forceinline__ void ffma2(unsigned long long &d,
                                      unsigned long long a,
                                      unsigned long long b) {
    asm("fma.rn.f32x2 %0, %1, %2, %0;" : "+l"(d) : "l"(a), "l"(b));
}

// ---------------- fp32 GEMM via FFMA2: C[M,N] = A[M,K] @ B[K,N] ------------
// BM=BN=128, BK=16, 128 threads, 16x8 per thread (accum packed along M).
// Requires M%128==0, K%16==0, N%4==0 (true for all calls). N-edge guarded.
#define BM 128
#define BN 128
#define BK 16
#define LDS_PAD 4

__global__ __launch_bounds__(128) void gemm2_kernel(
    const float* __restrict__ A, const float* __restrict__ B,
    float* __restrict__ C, int M, int N, int K)
{
    __shared__ float As[2][BK][BM + LDS_PAD];   // stored transposed: As[k][m]
    __shared__ float Bs[2][BK][BN + LDS_PAD];   // Bs[k][n]

    const int tid = threadIdx.x;
    const int tx  = tid & 15;          // col group: 8 cols each
    const int ty  = tid >> 4;          // row group: 16 rows each
    const int rowBase = blockIdx.y * BM;
    const int colBase = blockIdx.x * BN;

    // A load: thread owns row (rowBase + tid), 16 k's per tile
    const float* Aptr = A + (size_t)(rowBase + tid) * K;
    // B load: bK = tid>>3 (0..15), 16 consecutive cols at bC
    const int bK = tid >> 3;
    const int bC = (tid & 7) * 16;

    unsigned long long acc[8][8];      // [m-pair][n]
    #pragma unroll
    for (int i = 0; i < 8; i++)
        #pragma unroll
        for (int j = 0; j < 8; j++) acc[i][j] = 0ULL;

    float4 aReg[4], bReg[4];

    // prologue: load tile 0 into regs, then smem buf 0
    #pragma unroll
    for (int f = 0; f < 4; f++)
        aReg[f] = *(const float4*)(Aptr + f * 4);
    #pragma unroll
    for (int f = 0; f < 4; f++) {
        const int col = colBase + bC + f * 4;
        bReg[f] = (col < N) ? *(const float4*)(B + (size_t)bK * N + col)
                            : make_float4(0.f, 0.f, 0.f, 0.f);
    }
    #pragma unroll
    for (int f = 0; f < 4; f++) {
        As[0][f * 4 + 0][tid] = aReg[f].x;
        As[0][f * 4 + 1][tid] = aReg[f].y;
        As[0][f * 4 + 2][tid] = aReg[f].z;
        As[0][f * 4 + 3][tid] = aReg[f].w;
        *(float4*)&Bs[0][bK][bC + f * 4] = bReg[f];
    }
    __syncthreads();

    int buf = 0;
    for (int k0 = 0; k0 < K; k0 += BK) {
        const bool more = (k0 + BK) < K;
        if (more) {
            #pragma unroll
            for (int f = 0; f < 4; f++)
                aReg[f] = *(const float4*)(Aptr + k0 + BK + f * 4);
            #pragma unroll
            for (int f = 0; f < 4; f++) {
                const int col = colBase + bC + f * 4;
                bReg[f] = (col < N)
                    ? *(const float4*)(B + (size_t)(k0 + BK + bK) * N + col)
                    : make_float4(0.f, 0.f, 0.f, 0.f);
            }
        }

        #pragma unroll
        for (int kk = 0; kk < BK; kk++) {
            float4 a0 = *(const float4*)&As[buf][kk][ty * 16];
            float4 a1 = *(const float4*)&As[buf][kk][ty * 16 + 4];
            float4 a2 = *(const float4*)&As[buf][kk][ty * 16 + 8];
            float4 a3 = *(const float4*)&As[buf][kk][ty * 16 + 12];
            float4 b0 = *(const float4*)&Bs[buf][kk][tx * 8];
            float4 b1 = *(const float4*)&Bs[buf][kk][tx * 8 + 4];

            // a-pairs: reinterpret consecutive float pairs as packed f32x2
            unsigned long long ap[8];
            ap[0] = ((unsigned long long*)&a0)[0];
            ap[1] = ((unsigned long long*)&a0)[1];
            ap[2] = ((unsigned long long*)&a1)[0];
            ap[3] = ((unsigned long long*)&a1)[1];
            ap[4] = ((unsigned long long*)&a2)[0];
            ap[5] = ((unsigned long long*)&a2)[1];
            ap[6] = ((unsigned long long*)&a3)[0];
            ap[7] = ((unsigned long long*)&a3)[1];
            // b duplicated into both halves
            unsigned long long bp[8];
            bp[0] = pack2(b0.x, b0.x); bp[1] = pack2(b0.y, b0.y);
            bp[2] = pack2(b0.z, b0.z); bp[3] = pack2(b0.w, b0.w);
            bp[4] = pack2(b1.x, b1.x); bp[5] = pack2(b1.y, b1.y);
            bp[6] = pack2(b1.z, b1.z); bp[7] = pack2(b1.w, b1.w);

            #pragma unroll
            for (int i = 0; i < 8; i++)
                #pragma unroll
                for (int j = 0; j < 8; j++)
                    ffma2(acc[i][j], ap[i], bp[j]);
        }

        if (more) {
            const int nb = buf ^ 1;
            #pragma unroll
            for (int f = 0; f < 4; f++) {
                As[nb][f * 4 + 0][tid] = aReg[f].x;
                As[nb][f * 4 + 1][tid] = aReg[f].y;
                As[nb][f * 4 + 2][tid] = aReg[f].z;
                As[nb][f * 4 + 3][tid] = aReg[f].w;
                *(float4*)&Bs[nb][bK][bC + f * 4] = bReg[f];
            }
            __syncthreads();
            buf = nb;
        }
    }

    // epilogue: acc[i][j] holds rows (ty*16 + 2i, +2i+1), col tx*8 + j
    #pragma unroll
    for (int i = 0; i < 8; i++) {
        const int r0 = rowBase + ty * 16 + 2 * i;
        float lo[8], hi[8];
        #pragma unroll
        for (int j = 0; j < 8; j++) {
            float2 v = *(float2*)&acc[i][j];
            lo[j] = v.x; hi[j] = v.y;
        }
        #pragma unroll
        for (int half = 0; half < 2; half++) {
            const int col = colBase + tx * 8 + half * 4;
            if (col < N) {
                *(float4*)(C + (size_t)r0 * N + col) =
                    make_float4(lo[half*4+0], lo[half*4+1], lo[half*4+2], lo[half*4+3]);
                *(float4*)(C + (size_t)(r0 + 1) * N + col) =
                    make_float4(hi[half*4+0], hi[half*4+1], hi[half*4+2], hi[half*4+3]);
            }
        }
    }
}

// ---------------- causal depthwise conv1d (k=4) + bias + SiLU --------------
__global__ __launch_bounds__(256) void conv_kernel(
    const float* __restrict__ conv_w, const float* __restrict__ conv_b)
{
    const int l = blockIdx.x;
    const int b = blockIdx.y;
    const size_t orow = (size_t)(b * SEQLEN + l);

    for (int c = threadIdx.x; c < CONVDIM; c += 256) {
        float s = conv_b[c];
        #pragma unroll
        for (int k = 0; k < DCONV; k++) {
            const int ls = l - (DCONV - 1) + k;
            if (ls >= 0)
                s = fmaf(g_zxbcdt[((size_t)(b * SEQLEN + ls)) * NPROJ + DINNER + c],
                         conv_w[c * DCONV + k], s);
        }
        const float sil = s / (1.f + __expf(-s));
        g_xbc[orow * CONVDIM + c] = sil;
    }
}

// ---------------- dt = softplus(dt_raw + dt_bias) --------------------------
__global__ __launch_bounds__(256) void dt_kernel(const float* __restrict__ dt_bias)
{
    const int i = blockIdx.x * 256 + threadIdx.x;   // over MROWS*NH
    if (i >= MROWS * NH) return;
    const int h = i & (NH - 1);
    const int row = i >> 5;
    const float v = g_zxbcdt[(size_t)row * NPROJ + (DINNER + CONVDIM) + h] + dt_bias[h];
    g_dt[i] = (v > 20.f) ? v : log1pf(expf(v));
}

// ---------------- sequential selective scan (2-D thread blocking) ----------
// Block = one (b, h). 128 threads: pc = tid>>3 (16 chunks of 4 p-rows),
// nc = tid&7 (8 chunks of 8 states). Each thread owns a 4x8 (p,n) block of
// state in registers; acc reduced over the 8 nc lanes with 3 shfls.
#define SCHUNK 32
__global__ __launch_bounds__(128) void scan_kernel(
    const float* __restrict__ A_log, const float* __restrict__ Dv)
{
    __shared__ float sB[SCHUNK][DSTATE];
    __shared__ float sC[SCHUNK][DSTATE];
    __shared__ float sx[SCHUNK][HEADDIM];
    __shared__ float sdt[SCHUNK];

    const int bh = blockIdx.x;
    const int b = bh >> 5, h = bh & (NH - 1);
    const int tid = threadIdx.x;
    const int nc = tid & 7;          // state chunk: n in [8*nc, 8*nc+8)
    const int pc = tid >> 3;         // p chunk:     p in [4*pc, 4*pc+4)
    const int n0 = nc * 8;
    const int p0 = pc * 4;

    const float Aneg = -__expf(A_log[h]);
    const float Dh   = Dv[h];

    const float* dptr = g_dt + (size_t)b * SEQLEN * NH + h;
    float* ybase = g_y + (size_t)b * SEQLEN * DINNER + h * HEADDIM + p0;

    float hs[4][8];
    #pragma unroll
    for (int p = 0; p < 4; p++)
        #pragma unroll
        for (int j = 0; j < 8; j++) hs[p][j] = 0.f;

    for (int t0 = 0; t0 < SEQLEN; t0 += SCHUNK) {
        __syncthreads();    // previous chunk fully consumed
        // cooperative stage: SCHUNK steps x 64 floats each of B, C, x
        #pragma unroll
        for (int r = 0; r < (SCHUNK * 64 / 128); r++) {
            const int idx = tid + r * 128;
            const int t = idx >> 6, j = idx & 63;
            const size_t rb = (size_t)(b * SEQLEN + t0 + t) * CONVDIM;
            sB[t][j] = g_xbc[rb + DINNER + j];
            sC[t][j] = g_xbc[rb + DINNER + DSTATE + j];
            sx[t][j] = g_xbc[rb + h * HEADDIM + j];
        }
        if (tid < SCHUNK) sdt[tid] = dptr[(size_t)(t0 + tid) * NH];
        __syncthreads();

        #pragma unroll 4
        for (int tt = 0; tt < SCHUNK; tt++) {
            const float dtv = sdt[tt];
            const float dA = __expf(dtv * Aneg);
            const float4 xv = *(const float4*)&sx[tt][p0];
            const float4 b0 = *(const float4*)&sB[tt][n0];
            const float4 b1 = *(const float4*)&sB[tt][n0 + 4];
            const float4 c0 = *(const float4*)&sC[tt][n0];
            const float4 c1 = *(const float4*)&sC[tt][n0 + 4];
            float gb[8];
            gb[0] = dtv * b0.x; gb[1] = dtv * b0.y; gb[2] = dtv * b0.z; gb[3] = dtv * b0.w;
            gb[4] = dtv * b1.x; gb[5] = dtv * b1.y; gb[6] = dtv * b1.z; gb[7] = dtv * b1.w;
            const float cv[8] = {c0.x, c0.y, c0.z, c0.w, c1.x, c1.y, c1.z, c1.w};
            const float xp[4] = {xv.x, xv.y, xv.z, xv.w};
            float acc[4];
            #pragma unroll
            for (int p = 0; p < 4; p++) {
                acc[p] = 0.f;
                #pragma unroll
                for (int j = 0; j < 8; j++) {
                    hs[p][j] = fmaf(hs[p][j], dA, xp[p] * gb[j]);
                    acc[p] = fmaf(hs[p][j], cv[j], acc[p]);
                }
            }
            #pragma unroll
            for (int off = 1; off < 8; off <<= 1) {
                #pragma unroll
                for (int p = 0; p < 4; p++)
                    acc[p] += __shfl_xor_sync(0xffffffffu, acc[p], off);
            }
            if (nc == 0) {
                float4 o;
                o.x = acc[0] + Dh * xp[0];
                o.y = acc[1] + Dh * xp[1];
                o.z = acc[2] + Dh * xp[2];
                o.w = acc[3] + Dh * xp[3];
                *(float4*)(ybase + (size_t)(t0 + tt) * DINNER) = o;
            }
        }
    }
}

// ---------------- y = rmsnorm(y * silu(z)) * norm_w (in place) -------------
__global__ __launch_bounds__(256) void gatenorm_kernel(const float* __restrict__ norm_w)
{
    const int row = blockIdx.x;
    const float* zrow = g_zxbcdt + (size_t)row * NPROJ;   // z = first DINNER cols
    float* yrow = g_y + (size_t)row * DINNER;

    float v[8];
    float ss = 0.f;
    #pragma unroll
    for (int j = 0; j < 8; j++) {
        const int i = threadIdx.x + j * 256;
        const float z = zrow[i];
        const float g = yrow[i] * (z / (1.f + __expf(-z)));
        v[j] = g;
        ss = fmaf(g, g, ss);
    }
    #pragma unroll
    for (int o = 16; o; o >>= 1) ss += __shfl_xor_sync(0xffffffffu, ss, o);

    __shared__ float red[8];
    __shared__ float s_rstd;
    if ((threadIdx.x & 31) == 0) red[threadIdx.x >> 5] = ss;
    __syncthreads();
    if (threadIdx.x == 0) {
        float t = 0.f;
        #pragma unroll
        for (int w = 0; w < 8; w++) t += red[w];
        s_rstd = rsqrtf(t / (float)DINNER + 1e-5f);
    }
    __syncthreads();
    const float rstd = s_rstd;

    #pragma unroll
    for (int j = 0; j < 8; j++) {
        const int i = threadIdx.x + j * 256;
        yrow[i] = v[j] * rstd * norm_w[i];
    }
}

// ---------------- launch ----------------------------------------------------
extern "C" void kernel_launch(void* const* d_in, const int* in_sizes, int n_in,
                              void* d_out, int out_size)
{
    const float* x       = (const float*)d_in[0];
    const float* W_in    = (const float*)d_in[1];
    const float* conv_w  = (const float*)d_in[2];
    const float* conv_b  = (const float*)d_in[3];
    const float* dt_bias = (const float*)d_in[4];
    const float* A_log   = (const float*)d_in[5];
    const float* Dvec    = (const float*)d_in[6];
    const float* norm_w  = (const float*)d_in[7];
    const float* W_out   = (const float*)d_in[8];
    float* out = (float*)d_out;

    void *p_zx, *p_y;
    cudaGetSymbolAddress(&p_zx, g_zxbcdt);
    cudaGetSymbolAddress(&p_y,  g_y);
    float* zx = (float*)p_zx;
    float* y  = (float*)p_y;

    // 1) in-projection: zxbcdt = x @ W_in   [8192,1024]@[1024,4256]
    {
        dim3 grid((NPROJ + BN - 1) / BN, MROWS / BM);
        gemm2_kernel<<<grid, 128>>>(x, W_in, zx, MROWS, NPROJ, DMODEL);
    }
    // 2) conv + SiLU
    conv_kernel<<<dim3(SEQLEN, BATCH), 256>>>(conv_w, conv_b);
    // 3) dt softplus
    dt_kernel<<<(MROWS * NH + 255) / 256, 256>>>(dt_bias);
    // 4) selective scan
    scan_kernel<<<BATCH * NH, 128>>>(A_log, Dvec);
    // 5) gate + rmsnorm (in place on g_y)
    gatenorm_kernel<<<MROWS, 256>>>(norm_w);
    // 6) out-projection: out = y @ W_out   [8192,2048]@[2048,1024]
    {
        dim3 grid(DMODEL / BN, MROWS / BM);
        gemm2_kernel<<<grid, 128>>>(y, W_out, out, MROWS, DMODEL, DINNER);
    }
}